// round 3
// baseline (speedup 1.0000x reference)
#include <cuda_runtime.h>
#include <cuda_bf16.h>
#include <math.h>

// Problem constants
#define BB   32768
#define NM   20
#define DM   172      // message dim
#define TT   100      // time feature dim
#define EE   272      // E = D + T
#define HD_  136
#define E2   544      // H * E (also 2E)
#define FC1K 444      // E + D

__device__ __constant__ float kSCALE = 0.08574929257125442f; // 1/sqrt(136)

// ---------------- device scratch (static, no runtime alloc) ----------------
__device__ float g_qv[EE];                 // wq time-part @ cos(time_b) + bq
__device__ float g_wf[2 * EE * EE];        // Wf_h = out_proj[:,h] @ wv_h
__device__ float g_co[EE];                 // out_proj @ bv + out_b
__device__ float g_aqkT[DM * E2];          // [d][e2] e2 = h*272+e  (pre-scaled)
__device__ float g_cqk[E2];                // per-e2 const (pre-scaled)
__device__ float g_GT[E2 * DM];            // [e2][d]
__device__ float g_cvalid[DM];             // fc1[:, :E]@co + fc1_b
__device__ float g_gsrcT[DM * DM];         // [s][d] = fc1_w[d][E+s]
__device__ float g_fc2T[DM * DM];          // [k][d]
__device__ float g_mctx[(size_t)BB * E2];  // attn-weighted msgs, [b][e2]
__device__ unsigned char g_inv[BB];

// ---------------- precompute kernels ----------------
__global__ void prep_qv(const float* __restrict__ ipw, const float* __restrict__ ipb,
                        const float* __restrict__ tb) {
    int r = blockIdx.x * blockDim.x + threadIdx.x;
    if (r >= EE) return;
    float s = ipb[r];
    for (int t = 0; t < TT; t++) s = fmaf(ipw[r * EE + DM + t], cosf(tb[t]), s);
    g_qv[r] = s;
}

__global__ void prep_wf(const float* __restrict__ ipw, const float* __restrict__ ipb,
                        const float* __restrict__ opw, const float* __restrict__ opb) {
    int idx = blockIdx.x * blockDim.x + threadIdx.x;
    if (idx < 2 * EE * EE) {
        int h = idx / (EE * EE);
        int r = idx - h * EE * EE;
        int i = r / EE, e = r - (r / EE) * EE;
        float s = 0.f;
        for (int j = 0; j < HD_; j++)
            s = fmaf(opw[i * EE + h * HD_ + j], ipw[(2 * EE + h * HD_ + j) * EE + e], s);
        g_wf[idx] = s;
    } else if (idx < 2 * EE * EE + EE) {
        int i = idx - 2 * EE * EE;
        float s = opb[i];
        for (int k = 0; k < EE; k++) s = fmaf(opw[i * EE + k], ipb[2 * EE + k], s);
        g_co[i] = s;
    }
}

__global__ void prep_aqk(const float* __restrict__ ipw) {
    int idx = blockIdx.x * blockDim.x + threadIdx.x;
    if (idx < DM * E2) {
        int d = idx / E2, e2 = idx - d * E2;
        int h = e2 / EE, e = e2 - h * EE;
        float s = 0.f;
        for (int j = 0; j < HD_; j++)
            s = fmaf(ipw[(EE + h * HD_ + j) * EE + e], ipw[(h * HD_ + j) * EE + d], s);
        g_aqkT[idx] = s * kSCALE;
    } else if (idx < DM * E2 + E2) {
        int e2 = idx - DM * E2;
        int h = e2 / EE, e = e2 - h * EE;
        float s = 0.f;
        for (int j = 0; j < HD_; j++)
            s = fmaf(ipw[(EE + h * HD_ + j) * EE + e], g_qv[h * HD_ + j], s);
        g_cqk[e2] = s * kSCALE;
    }
}

__global__ void prep_g(const float* __restrict__ fc1w, const float* __restrict__ fc1b,
                       const float* __restrict__ fc2w) {
    int idx = blockIdx.x * blockDim.x + threadIdx.x;
    if (idx < DM * E2) {
        int d = idx / E2, e2 = idx - d * E2;
        int h = e2 / EE, e = e2 - h * EE;
        float s = 0.f;
        for (int i = 0; i < EE; i++)
            s = fmaf(fc1w[d * FC1K + i], g_wf[(h * EE + i) * EE + e], s);
        g_GT[e2 * DM + d] = s;
    } else if (idx < DM * E2 + DM) {
        int d = idx - DM * E2;
        float s = fc1b[d];
        for (int i = 0; i < EE; i++) s = fmaf(fc1w[d * FC1K + i], g_co[i], s);
        g_cvalid[d] = s;
    } else if (idx < DM * E2 + DM + DM * DM) {
        int r = idx - (DM * E2 + DM);
        int d = r / DM, s2 = r - d * DM;
        g_gsrcT[s2 * DM + d] = fc1w[d * FC1K + EE + s2];
    } else if (idx < DM * E2 + DM + 2 * DM * DM) {
        int r = idx - (DM * E2 + DM + DM * DM);
        int d = r / DM, k = r - d * DM;
        g_fc2T[k * DM + d] = fc2w[d * DM + k];
    }
}

// ---------------- K1: time-feat + qk + attention + mctx ----------------
// 16 batch rows / block, 288 threads.
// smem floats: tf 32000 | src 2752 | qk 8704 | attn 640 | timev 320 | twb 200
#define K1_SMEM ((16*NM*TT + 16*DM + 16*E2 + 16*2*NM + 16*NM + 2*TT) * 4)

__global__ void __launch_bounds__(288, 1)
k1_attn(const float* __restrict__ msg, const float* __restrict__ timeb,
        const float* __restrict__ tw, const float* __restrict__ tb) {
    extern __shared__ float sm[];
    float* tf    = sm;                  // [16][2000]
    float* src   = tf + 16 * NM * TT;   // [16][172]
    float* qk    = src + 16 * DM;       // [16][544]
    float* attn  = qk + 16 * E2;        // [32][20]  (scores then attn)
    float* timev = attn + 16 * 2 * NM;  // [16][20]
    float* twb   = timev + 16 * NM;     // [200]
    const int tid = threadIdx.x;
    const int b0 = blockIdx.x * 16;

    for (int i = tid; i < 2 * TT; i += 288) twb[i] = (i < TT) ? tw[i] : tb[i - TT];
    for (int i = tid; i < 16 * NM; i += 288)
        timev[i] = timeb[(b0 + i / NM) * NM + (i % NM)];
    __syncthreads();

    if (tid < 16) {
        bool all_neg = true;
        for (int n = 0; n < NM; n++) all_neg = all_neg && (timev[tid * NM + n] < 0.0f);
        g_inv[b0 + tid] = (unsigned char)all_neg;
    }
    for (int i = tid; i < 16 * NM * TT; i += 288) {
        int b = i / (NM * TT);
        int r = i - b * NM * TT;
        int n = r / TT, t = r - n * TT;
        float dl = timev[b * NM + n] - timev[b * NM + NM - 1];
        tf[i] = cosf(fmaf(dl, twb[t], twb[TT + t]));
    }
    for (int i = tid; i < 16 * DM; i += 288) {
        int b = i / DM, d = i - (i / DM) * DM;
        src[i] = msg[((b0 + b) * NM + NM - 1) * DM + d];
    }
    __syncthreads();

    // ---- qk[b][e2] = Aqk @ src + cqk (batched GEMV, register tiled) ----
    if (tid < EE) {
        float acc0[16], acc1[16];
#pragma unroll
        for (int t = 0; t < 16; t++) { acc0[t] = 0.f; acc1[t] = 0.f; }
        for (int k = 0; k < DM; k += 2) {
            float w0a = g_aqkT[k * E2 + tid];
            float w1a = g_aqkT[k * E2 + EE + tid];
            float w0b = g_aqkT[(k + 1) * E2 + tid];
            float w1b = g_aqkT[(k + 1) * E2 + EE + tid];
#pragma unroll
            for (int t = 0; t < 16; t++) {
                float a = src[t * DM + k];
                float b = src[t * DM + k + 1];
                acc0[t] = fmaf(w0a, a, fmaf(w0b, b, acc0[t]));
                acc1[t] = fmaf(w1a, a, fmaf(w1b, b, acc1[t]));
            }
        }
        float c0 = g_cqk[tid], c1 = g_cqk[EE + tid];
#pragma unroll
        for (int t = 0; t < 16; t++) {
            qk[t * E2 + tid] = acc0[t] + c0;
            qk[t * E2 + EE + tid] = acc1[t] + c1;
        }
    }
    __syncthreads();

    // ---- scores: warp per 2 batch rows ----
    const int w = tid >> 5, lane = tid & 31;
    if (w < 8) {
        for (int bbr = 0; bbr < 2; bbr++) {
            int bi = w * 2 + bbr;
            const float* qk0 = qk + bi * E2;
            const float* qk1 = qk0 + EE;
            for (int n = 0; n < NM; n++) {
                float s0 = 0.f, s1 = 0.f;
                const float* mrow = msg + ((size_t)(b0 + bi) * NM + n) * DM;
                for (int d = lane; d < DM; d += 32) {
                    float m = mrow[d];
                    s0 = fmaf(qk0[d], m, s0);
                    s1 = fmaf(qk1[d], m, s1);
                }
                const float* trow = tf + bi * NM * TT + n * TT;
                for (int t = lane; t < TT; t += 32) {
                    float f = trow[t];
                    s0 = fmaf(qk0[DM + t], f, s0);
                    s1 = fmaf(qk1[DM + t], f, s1);
                }
#pragma unroll
                for (int off = 16; off; off >>= 1) {
                    s0 += __shfl_xor_sync(0xffffffffu, s0, off);
                    s1 += __shfl_xor_sync(0xffffffffu, s1, off);
                }
                if (lane == 0) {
                    bool mk = timev[bi * NM + n] < 0.0f;
                    attn[(bi * 2) * NM + n]     = mk ? -1e9f : s0;
                    attn[(bi * 2 + 1) * NM + n] = mk ? -1e9f : s1;
                }
            }
        }
    }
    __syncthreads();

    // ---- softmax: one thread per (b,h) ----
    if (tid < 32) {
        float* row = attn + tid * NM;
        float mx = -3.4e38f;
        for (int n = 0; n < NM; n++) mx = fmaxf(mx, row[n]);
        float sum = 0.f;
        for (int n = 0; n < NM; n++) { float e = __expf(row[n] - mx); row[n] = e; sum += e; }
        float r = 1.0f / sum;
        for (int n = 0; n < NM; n++) row[n] *= r;
    }
    __syncthreads();

    // ---- mctx[b][e2] = sum_n attn * msgs ----
    if (tid < EE) {
        float a0[16], a1[16];
#pragma unroll
        for (int t = 0; t < 16; t++) { a0[t] = 0.f; a1[t] = 0.f; }
        if (tid < DM) {
            for (int n = 0; n < NM; n++) {
#pragma unroll
                for (int b = 0; b < 16; b++) {
                    float m = msg[((size_t)(b0 + b) * NM + n) * DM + tid];
                    a0[b] = fmaf(attn[(b * 2) * NM + n], m, a0[b]);
                    a1[b] = fmaf(attn[(b * 2 + 1) * NM + n], m, a1[b]);
                }
            }
        } else {
            int t0 = tid - DM;
            for (int n = 0; n < NM; n++) {
#pragma unroll
                for (int b = 0; b < 16; b++) {
                    float f = tf[b * NM * TT + n * TT + t0];
                    a0[b] = fmaf(attn[(b * 2) * NM + n], f, a0[b]);
                    a1[b] = fmaf(attn[(b * 2 + 1) * NM + n], f, a1[b]);
                }
            }
        }
#pragma unroll
        for (int b = 0; b < 16; b++) {
            g_mctx[(size_t)(b0 + b) * E2 + tid]      = a0[b];
            g_mctx[(size_t)(b0 + b) * E2 + EE + tid] = a1[b];
        }
    }
}

// ---------------- K2: fused out_proj+fc1 -> relu -> fc2 ----------------
#define K2_SMEM ((16*E2 + 16*DM + 16*DM) * 4 + 64)

__global__ void __launch_bounds__(192)
k2_out(const float* __restrict__ msg, const float* __restrict__ fc1b,
       const float* __restrict__ fc2b, float* __restrict__ out) {
    extern __shared__ float sm[];
    float* mctx = sm;               // [16][544]
    float* src  = mctx + 16 * E2;   // [16][172]
    float* hbuf = src + 16 * DM;    // [16][172]
    int*   inv  = (int*)(hbuf + 16 * DM);
    const int tid = threadIdx.x;
    const int b0 = blockIdx.x * 16;

    if (tid < 16) inv[tid] = (int)g_inv[b0 + tid];
    __syncthreads();
    for (int i = tid; i < 16 * E2; i += 192) {
        int b = i / E2;
        mctx[i] = inv[b] ? 0.0f : g_mctx[(size_t)(b0 + b) * E2 + (i - b * E2)];
    }
    for (int i = tid; i < 16 * DM; i += 192) {
        int b = i / DM;
        src[i] = msg[((size_t)(b0 + b) * NM + NM - 1) * DM + (i - b * DM)];
    }
    __syncthreads();

    if (tid < DM) {
        float acc[16];
#pragma unroll
        for (int t = 0; t < 16; t++) acc[t] = inv[t] ? fc1b[tid] : g_cvalid[tid];
        for (int k = 0; k < E2; k += 2) {
            float wa = g_GT[k * DM + tid];
            float wb = g_GT[(k + 1) * DM + tid];
#pragma unroll
            for (int t = 0; t < 16; t++)
                acc[t] = fmaf(wa, mctx[t * E2 + k], fmaf(wb, mctx[t * E2 + k + 1], acc[t]));
        }
        for (int s = 0; s < DM; s += 2) {
            float wa = g_gsrcT[s * DM + tid];
            float wb = g_gsrcT[(s + 1) * DM + tid];
#pragma unroll
            for (int t = 0; t < 16; t++)
                acc[t] = fmaf(wa, src[t * DM + s], fmaf(wb, src[t * DM + s + 1], acc[t]));
        }
#pragma unroll
        for (int t = 0; t < 16; t++) hbuf[t * DM + tid] = fmaxf(acc[t], 0.0f);
    }
    __syncthreads();

    if (tid < DM) {
        float acc[16];
        float bb = fc2b[tid];
#pragma unroll
        for (int t = 0; t < 16; t++) acc[t] = bb;
        for (int k = 0; k < DM; k += 2) {
            float wa = g_fc2T[k * DM + tid];
            float wb = g_fc2T[(k + 1) * DM + tid];
#pragma unroll
            for (int t = 0; t < 16; t++)
                acc[t] = fmaf(wa, hbuf[t * DM + k], fmaf(wb, hbuf[t * DM + k + 1], acc[t]));
        }
#pragma unroll
        for (int t = 0; t < 16; t++)
            out[(size_t)(b0 + t) * DM + tid] = acc[t];
    }
}

// ---------------- launch ----------------
extern "C" void kernel_launch(void* const* d_in, const int* in_sizes, int n_in,
                              void* d_out, int out_size) {
    const float* msg   = (const float*)d_in[0];   // (B,N,D)
    const float* timeb = (const float*)d_in[1];   // (B,N)
    // d_in[2] = memory (unused by reference)
    const float* tw    = (const float*)d_in[3];   // (T,)
    const float* tb    = (const float*)d_in[4];   // (T,)
    const float* ipw   = (const float*)d_in[5];   // (3E,E)
    const float* ipb   = (const float*)d_in[6];   // (3E,)
    const float* opw   = (const float*)d_in[7];   // (E,E)
    const float* opb   = (const float*)d_in[8];   // (E,)
    const float* fc1w  = (const float*)d_in[9];   // (D,E+D)
    const float* fc1b  = (const float*)d_in[10];  // (D,)
    const float* fc2w  = (const float*)d_in[11];  // (D,D)
    const float* fc2b  = (const float*)d_in[12];  // (D,)
    float* out = (float*)d_out;

    cudaFuncSetAttribute(k1_attn, cudaFuncAttributeMaxDynamicSharedMemorySize, K1_SMEM);
    cudaFuncSetAttribute(k2_out,  cudaFuncAttributeMaxDynamicSharedMemorySize, K2_SMEM);

    prep_qv<<<2, 256>>>(ipw, ipb, tb);
    prep_wf<<<(2 * EE * EE + EE + 255) / 256, 256>>>(ipw, ipb, opw, opb);
    prep_aqk<<<(DM * E2 + E2 + 255) / 256, 256>>>(ipw);
    prep_g<<<(DM * E2 + DM + 2 * DM * DM + 255) / 256, 256>>>(fc1w, fc1b, fc2w);

    k1_attn<<<BB / 16, 288, K1_SMEM>>>(msg, timeb, tw, tb);
    k2_out<<<BB / 16, 192, K2_SMEM>>>(msg, fc1b, fc2b, out);
}

// round 4
// speedup vs baseline: 1.6790x; 1.6790x over previous
#include <cuda_runtime.h>
#include <cuda_bf16.h>
#include <math.h>

// Problem constants
#define BB   32768
#define NM   20
#define DM   172      // message dim
#define TT   100      // time feature dim
#define EE   272      // E = D + T
#define HD_  136
#define E2   544      // H * E (also 2E)
#define FC1K 444      // E + D

__device__ __constant__ float kSCALE = 0.08574929257125442f; // 1/sqrt(136)

// ---------------- device scratch (static, no runtime alloc) ----------------
__device__ float g_qv[EE];                 // wq time-part @ cos(time_b) + bq
__device__ float g_wf[2 * EE * EE];        // Wf_h = out_proj[:,h] @ wv_h
__device__ float g_co[EE];                 // out_proj @ bv + out_b
__device__ float g_aqkT[DM * E2];          // [d][e2] e2 = h*272+e  (pre-scaled)
__device__ float g_cqk[E2];                // per-e2 const (pre-scaled)
__device__ float g_GT[E2 * DM];            // [e2][d]
__device__ float g_cvalid[DM];             // fc1[:, :E]@co + fc1_b
__device__ float g_gsrcT[DM * DM];         // [s][d] = fc1_w[d][E+s]
__device__ float g_fc2T[DM * DM];          // [k][d]
__device__ float g_mctx[(size_t)BB * E2];  // attn-weighted msgs, [b][e2]
__device__ unsigned char g_inv[BB];

// ---------------- precompute kernels ----------------
__global__ void prep_qv(const float* __restrict__ ipw, const float* __restrict__ ipb,
                        const float* __restrict__ tb) {
    int r = blockIdx.x * blockDim.x + threadIdx.x;
    if (r >= EE) return;
    float s = ipb[r];
    for (int t = 0; t < TT; t++) s = fmaf(ipw[r * EE + DM + t], cosf(tb[t]), s);
    g_qv[r] = s;
}

__global__ void prep_wf(const float* __restrict__ ipw, const float* __restrict__ ipb,
                        const float* __restrict__ opw, const float* __restrict__ opb) {
    int idx = blockIdx.x * blockDim.x + threadIdx.x;
    if (idx < 2 * EE * EE) {
        int h = idx / (EE * EE);
        int r = idx - h * EE * EE;
        int i = r / EE, e = r - (r / EE) * EE;
        float s = 0.f;
        for (int j = 0; j < HD_; j++)
            s = fmaf(opw[i * EE + h * HD_ + j], ipw[(2 * EE + h * HD_ + j) * EE + e], s);
        g_wf[idx] = s;
    } else if (idx < 2 * EE * EE + EE) {
        int i = idx - 2 * EE * EE;
        float s = opb[i];
        for (int k = 0; k < EE; k++) s = fmaf(opw[i * EE + k], ipb[2 * EE + k], s);
        g_co[i] = s;
    }
}

__global__ void prep_aqk(const float* __restrict__ ipw) {
    int idx = blockIdx.x * blockDim.x + threadIdx.x;
    if (idx < DM * E2) {
        int d = idx / E2, e2 = idx - d * E2;
        int h = e2 / EE, e = e2 - h * EE;
        float s = 0.f;
        for (int j = 0; j < HD_; j++)
            s = fmaf(ipw[(EE + h * HD_ + j) * EE + e], ipw[(h * HD_ + j) * EE + d], s);
        g_aqkT[idx] = s * kSCALE;
    } else if (idx < DM * E2 + E2) {
        int e2 = idx - DM * E2;
        int h = e2 / EE, e = e2 - h * EE;
        float s = 0.f;
        for (int j = 0; j < HD_; j++)
            s = fmaf(ipw[(EE + h * HD_ + j) * EE + e], g_qv[h * HD_ + j], s);
        g_cqk[e2] = s * kSCALE;
    }
}

__global__ void prep_g(const float* __restrict__ fc1w, const float* __restrict__ fc1b,
                       const float* __restrict__ fc2w) {
    int idx = blockIdx.x * blockDim.x + threadIdx.x;
    if (idx < DM * E2) {
        int d = idx / E2, e2 = idx - d * E2;
        int h = e2 / EE, e = e2 - h * EE;
        float s = 0.f;
        for (int i = 0; i < EE; i++)
            s = fmaf(fc1w[d * FC1K + i], g_wf[(h * EE + i) * EE + e], s);
        g_GT[e2 * DM + d] = s;
    } else if (idx < DM * E2 + DM) {
        int d = idx - DM * E2;
        float s = fc1b[d];
        for (int i = 0; i < EE; i++) s = fmaf(fc1w[d * FC1K + i], g_co[i], s);
        g_cvalid[d] = s;
    } else if (idx < DM * E2 + DM + DM * DM) {
        int r = idx - (DM * E2 + DM);
        int d = r / DM, s2 = r - d * DM;
        g_gsrcT[s2 * DM + d] = fc1w[d * FC1K + EE + s2];
    } else if (idx < DM * E2 + DM + 2 * DM * DM) {
        int r = idx - (DM * E2 + DM + DM * DM);
        int d = r / DM, k = r - d * DM;
        g_fc2T[k * DM + d] = fc2w[d * DM + k];
    }
}

// ---------------- K1: time-feat + qk + attention + mctx ----------------
// 16 batch rows / block, 288 threads, 3 blocks/SM.
// Time features recomputed via __cosf (no tf smem array).
// smem floats: src 2752 | qk 8704 | attn 640 | timev 320 | dl 320 | twb 200
#define K1_SMEM ((16*DM + 16*E2 + 16*2*NM + 16*NM + 16*NM + 2*TT) * 4)

__global__ void __launch_bounds__(288, 3)
k1_attn(const float* __restrict__ msg, const float* __restrict__ timeb,
        const float* __restrict__ tw, const float* __restrict__ tb) {
    extern __shared__ float sm[];
    float* src   = sm;                  // [16][172]
    float* qk    = src + 16 * DM;       // [16][544]
    float* attn  = qk + 16 * E2;        // [32][20]  (scores then attn)
    float* timev = attn + 16 * 2 * NM;  // [16][20]
    float* dls   = timev + 16 * NM;     // [16][20]  delta times
    float* twb   = dls + 16 * NM;       // [200]
    const int tid = threadIdx.x;
    const int b0 = blockIdx.x * 16;

    for (int i = tid; i < 2 * TT; i += 288) twb[i] = (i < TT) ? tw[i] : tb[i - TT];
    for (int i = tid; i < 16 * NM; i += 288)
        timev[i] = timeb[(b0 + i / NM) * NM + (i % NM)];
    __syncthreads();

    if (tid < 16) {
        bool all_neg = true;
        float t_last = timev[tid * NM + NM - 1];
        for (int n = 0; n < NM; n++) {
            float tv = timev[tid * NM + n];
            all_neg = all_neg && (tv < 0.0f);
            dls[tid * NM + n] = tv - t_last;
        }
        g_inv[b0 + tid] = (unsigned char)all_neg;
    }
    for (int i = tid; i < 16 * DM; i += 288) {
        int b = i / DM, d = i - (i / DM) * DM;
        src[i] = msg[((b0 + b) * NM + NM - 1) * DM + d];
    }
    __syncthreads();

    // ---- qk[b][e2] = Aqk @ src + cqk (batched GEMV, register tiled) ----
    if (tid < EE) {
        float acc0[16], acc1[16];
#pragma unroll
        for (int t = 0; t < 16; t++) { acc0[t] = 0.f; acc1[t] = 0.f; }
        for (int k = 0; k < DM; k += 2) {
            float w0a = g_aqkT[k * E2 + tid];
            float w1a = g_aqkT[k * E2 + EE + tid];
            float w0b = g_aqkT[(k + 1) * E2 + tid];
            float w1b = g_aqkT[(k + 1) * E2 + EE + tid];
#pragma unroll
            for (int t = 0; t < 16; t++) {
                float a = src[t * DM + k];
                float b = src[t * DM + k + 1];
                acc0[t] = fmaf(w0a, a, fmaf(w0b, b, acc0[t]));
                acc1[t] = fmaf(w1a, a, fmaf(w1b, b, acc1[t]));
            }
        }
        float c0 = g_cqk[tid], c1 = g_cqk[EE + tid];
#pragma unroll
        for (int t = 0; t < 16; t++) {
            qk[t * E2 + tid] = acc0[t] + c0;
            qk[t * E2 + EE + tid] = acc1[t] + c1;
        }
    }
    __syncthreads();

    // ---- scores: warp per 2 batch rows, time features recomputed ----
    const int w = tid >> 5, lane = tid & 31;
    if (w < 8) {
        for (int bbr = 0; bbr < 2; bbr++) {
            int bi = w * 2 + bbr;
            const float* qk0 = qk + bi * E2;
            const float* qk1 = qk0 + EE;
            for (int n = 0; n < NM; n++) {
                float s0 = 0.f, s1 = 0.f;
                const float* mrow = msg + ((size_t)(b0 + bi) * NM + n) * DM;
                for (int d = lane; d < DM; d += 32) {
                    float m = mrow[d];
                    s0 = fmaf(qk0[d], m, s0);
                    s1 = fmaf(qk1[d], m, s1);
                }
                float dl = dls[bi * NM + n];
                for (int t = lane; t < TT; t += 32) {
                    float f = __cosf(fmaf(dl, twb[t], twb[TT + t]));
                    s0 = fmaf(qk0[DM + t], f, s0);
                    s1 = fmaf(qk1[DM + t], f, s1);
                }
#pragma unroll
                for (int off = 16; off; off >>= 1) {
                    s0 += __shfl_xor_sync(0xffffffffu, s0, off);
                    s1 += __shfl_xor_sync(0xffffffffu, s1, off);
                }
                if (lane == 0) {
                    bool mk = timev[bi * NM + n] < 0.0f;
                    attn[(bi * 2) * NM + n]     = mk ? -1e9f : s0;
                    attn[(bi * 2 + 1) * NM + n] = mk ? -1e9f : s1;
                }
            }
        }
    }
    __syncthreads();

    // ---- softmax: one thread per (b,h) ----
    if (tid < 32) {
        float* row = attn + tid * NM;
        float mx = -3.4e38f;
        for (int n = 0; n < NM; n++) mx = fmaxf(mx, row[n]);
        float sum = 0.f;
        for (int n = 0; n < NM; n++) { float e = __expf(row[n] - mx); row[n] = e; sum += e; }
        float r = 1.0f / sum;
        for (int n = 0; n < NM; n++) row[n] *= r;
    }
    __syncthreads();

    // ---- mctx[b][e2] = sum_n attn * msgs  (time part recomputes cos) ----
    if (tid < EE) {
        float a0[16], a1[16];
#pragma unroll
        for (int t = 0; t < 16; t++) { a0[t] = 0.f; a1[t] = 0.f; }
        if (tid < DM) {
            for (int n = 0; n < NM; n++) {
#pragma unroll
                for (int b = 0; b < 16; b++) {
                    float m = msg[((size_t)(b0 + b) * NM + n) * DM + tid];
                    a0[b] = fmaf(attn[(b * 2) * NM + n], m, a0[b]);
                    a1[b] = fmaf(attn[(b * 2 + 1) * NM + n], m, a1[b]);
                }
            }
        } else {
            int t0 = tid - DM;
            float wt = twb[t0], bt = twb[TT + t0];
            for (int n = 0; n < NM; n++) {
#pragma unroll
                for (int b = 0; b < 16; b++) {
                    float f = __cosf(fmaf(dls[b * NM + n], wt, bt));
                    a0[b] = fmaf(attn[(b * 2) * NM + n], f, a0[b]);
                    a1[b] = fmaf(attn[(b * 2 + 1) * NM + n], f, a1[b]);
                }
            }
        }
#pragma unroll
        for (int b = 0; b < 16; b++) {
            g_mctx[(size_t)(b0 + b) * E2 + tid]      = a0[b];
            g_mctx[(size_t)(b0 + b) * E2 + EE + tid] = a1[b];
        }
    }
}

// ---------------- K2: fused out_proj+fc1 -> relu -> fc2 ----------------
#define K2_SMEM ((16*E2 + 16*DM + 16*DM) * 4 + 64)

__global__ void __launch_bounds__(192, 3)
k2_out(const float* __restrict__ msg, const float* __restrict__ fc1b,
       const float* __restrict__ fc2b, float* __restrict__ out) {
    extern __shared__ float sm[];
    float* mctx = sm;               // [16][544]
    float* src  = mctx + 16 * E2;   // [16][172]
    float* hbuf = src + 16 * DM;    // [16][172]
    int*   inv  = (int*)(hbuf + 16 * DM);
    const int tid = threadIdx.x;
    const int b0 = blockIdx.x * 16;

    if (tid < 16) inv[tid] = (int)g_inv[b0 + tid];
    __syncthreads();
    for (int i = tid; i < 16 * E2; i += 192) {
        int b = i / E2;
        mctx[i] = inv[b] ? 0.0f : g_mctx[(size_t)(b0 + b) * E2 + (i - b * E2)];
    }
    for (int i = tid; i < 16 * DM; i += 192) {
        int b = i / DM;
        src[i] = msg[((size_t)(b0 + b) * NM + NM - 1) * DM + (i - b * DM)];
    }
    __syncthreads();

    if (tid < DM) {
        float acc[16];
#pragma unroll
        for (int t = 0; t < 16; t++) acc[t] = inv[t] ? fc1b[tid] : g_cvalid[tid];
#pragma unroll 2
        for (int k = 0; k < E2; k += 2) {
            float wa = g_GT[k * DM + tid];
            float wb = g_GT[(k + 1) * DM + tid];
#pragma unroll
            for (int t = 0; t < 16; t++)
                acc[t] = fmaf(wa, mctx[t * E2 + k], fmaf(wb, mctx[t * E2 + k + 1], acc[t]));
        }
#pragma unroll 2
        for (int s = 0; s < DM; s += 2) {
            float wa = g_gsrcT[s * DM + tid];
            float wb = g_gsrcT[(s + 1) * DM + tid];
#pragma unroll
            for (int t = 0; t < 16; t++)
                acc[t] = fmaf(wa, src[t * DM + s], fmaf(wb, src[t * DM + s + 1], acc[t]));
        }
#pragma unroll
        for (int t = 0; t < 16; t++) hbuf[t * DM + tid] = fmaxf(acc[t], 0.0f);
    }
    __syncthreads();

    if (tid < DM) {
        float acc[16];
        float bb = fc2b[tid];
#pragma unroll
        for (int t = 0; t < 16; t++) acc[t] = bb;
#pragma unroll 2
        for (int k = 0; k < DM; k += 2) {
            float wa = g_fc2T[k * DM + tid];
            float wb = g_fc2T[(k + 1) * DM + tid];
#pragma unroll
            for (int t = 0; t < 16; t++)
                acc[t] = fmaf(wa, hbuf[t * DM + k], fmaf(wb, hbuf[t * DM + k + 1], acc[t]));
        }
#pragma unroll
        for (int t = 0; t < 16; t++)
            out[(size_t)(b0 + t) * DM + tid] = acc[t];
    }
}

// ---------------- launch ----------------
extern "C" void kernel_launch(void* const* d_in, const int* in_sizes, int n_in,
                              void* d_out, int out_size) {
    const float* msg   = (const float*)d_in[0];   // (B,N,D)
    const float* timeb = (const float*)d_in[1];   // (B,N)
    // d_in[2] = memory (unused by reference)
    const float* tw    = (const float*)d_in[3];   // (T,)
    const float* tb    = (const float*)d_in[4];   // (T,)
    const float* ipw   = (const float*)d_in[5];   // (3E,E)
    const float* ipb   = (const float*)d_in[6];   // (3E,)
    const float* opw   = (const float*)d_in[7];   // (E,E)
    const float* opb   = (const float*)d_in[8];   // (E,)
    const float* fc1w  = (const float*)d_in[9];   // (D,E+D)
    const float* fc1b  = (const float*)d_in[10];  // (D,)
    const float* fc2w  = (const float*)d_in[11];  // (D,D)
    const float* fc2b  = (const float*)d_in[12];  // (D,)
    float* out = (float*)d_out;

    cudaFuncSetAttribute(k1_attn, cudaFuncAttributeMaxDynamicSharedMemorySize, K1_SMEM);
    cudaFuncSetAttribute(k2_out,  cudaFuncAttributeMaxDynamicSharedMemorySize, K2_SMEM);

    prep_qv<<<2, 256>>>(ipw, ipb, tb);
    prep_wf<<<(2 * EE * EE + EE + 255) / 256, 256>>>(ipw, ipb, opw, opb);
    prep_aqk<<<(DM * E2 + E2 + 255) / 256, 256>>>(ipw);
    prep_g<<<(DM * E2 + DM + 2 * DM * DM + 255) / 256, 256>>>(fc1w, fc1b, fc2w);

    k1_attn<<<BB / 16, 288, K1_SMEM>>>(msg, timeb, tw, tb);
    k2_out<<<BB / 16, 192, K2_SMEM>>>(msg, fc1b, fc2b, out);
}

// round 6
// speedup vs baseline: 1.9400x; 1.1555x over previous
#include <cuda_runtime.h>
#include <cuda_bf16.h>
#include <math.h>

// Problem constants
#define BB   32768
#define NM   20
#define DM   172      // message dim
#define TT   100      // time feature dim
#define EE   272      // E = D + T
#define HD_  136
#define E2   544      // H * E (also 2E)
#define E2V  136      // E2/4
#define DMV  43       // DM/4
#define FC1K 444      // E + D

__device__ __constant__ float kSCALE = 0.08574929257125442f; // 1/sqrt(136)

// ---------------- device scratch (static, no runtime alloc) ----------------
__device__ float g_qv[EE];                 // wq time-part @ cos(time_b) + bq
__device__ float g_wf[2 * EE * EE];        // Wf_h = out_proj[:,h] @ wv_h
__device__ float g_co[EE];                 // out_proj @ bv + out_b
__device__ float g_aqkT[DM * E2];          // [d][e2] e2 = h*272+e  (pre-scaled)
__device__ float g_cqk[E2];                // per-e2 const (pre-scaled)
__device__ float g_GT[E2 * DM];            // [k][d]
__device__ float g_cvalid[DM];             // fc1[:, :E]@co + fc1_b
__device__ float g_gsrcT[DM * DM];         // [s][d] = fc1_w[d][E+s]
__device__ float g_fc2T[DM * DM];          // [k][d]
__device__ float g_mctx[(size_t)BB * E2];  // attn-weighted msgs, [b][e2]
__device__ unsigned char g_inv[BB];

// ---------------- precompute kernels ----------------
__global__ void prep_qv(const float* __restrict__ ipw, const float* __restrict__ ipb,
                        const float* __restrict__ tb) {
    int r = blockIdx.x * blockDim.x + threadIdx.x;
    if (r >= EE) return;
    float s = ipb[r];
    for (int t = 0; t < TT; t++) s = fmaf(ipw[r * EE + DM + t], cosf(tb[t]), s);
    g_qv[r] = s;
}

__global__ void prep_wf(const float* __restrict__ ipw, const float* __restrict__ ipb,
                        const float* __restrict__ opw, const float* __restrict__ opb) {
    int idx = blockIdx.x * blockDim.x + threadIdx.x;
    if (idx < 2 * EE * EE) {
        int h = idx / (EE * EE);
        int r = idx - h * EE * EE;
        int i = r / EE, e = r - (r / EE) * EE;
        float s = 0.f;
        for (int j = 0; j < HD_; j++)
            s = fmaf(opw[i * EE + h * HD_ + j], ipw[(2 * EE + h * HD_ + j) * EE + e], s);
        g_wf[idx] = s;
    } else if (idx < 2 * EE * EE + EE) {
        int i = idx - 2 * EE * EE;
        float s = opb[i];
        for (int k = 0; k < EE; k++) s = fmaf(opw[i * EE + k], ipb[2 * EE + k], s);
        g_co[i] = s;
    }
}

__global__ void prep_aqk(const float* __restrict__ ipw) {
    int idx = blockIdx.x * blockDim.x + threadIdx.x;
    if (idx < DM * E2) {
        int d = idx / E2, e2 = idx - d * E2;
        int h = e2 / EE, e = e2 - h * EE;
        float s = 0.f;
        for (int j = 0; j < HD_; j++)
            s = fmaf(ipw[(EE + h * HD_ + j) * EE + e], ipw[(h * HD_ + j) * EE + d], s);
        g_aqkT[idx] = s * kSCALE;
    } else if (idx < DM * E2 + E2) {
        int e2 = idx - DM * E2;
        int h = e2 / EE, e = e2 - h * EE;
        float s = 0.f;
        for (int j = 0; j < HD_; j++)
            s = fmaf(ipw[(EE + h * HD_ + j) * EE + e], g_qv[h * HD_ + j], s);
        g_cqk[e2] = s * kSCALE;
    }
}

__global__ void prep_g(const float* __restrict__ fc1w, const float* __restrict__ fc1b,
                       const float* __restrict__ fc2w) {
    int idx = blockIdx.x * blockDim.x + threadIdx.x;
    if (idx < DM * E2) {
        int d = idx / E2, e2 = idx - d * E2;
        int h = e2 / EE, e = e2 - h * EE;
        float s = 0.f;
        for (int i = 0; i < EE; i++)
            s = fmaf(fc1w[d * FC1K + i], g_wf[(h * EE + i) * EE + e], s);
        g_GT[e2 * DM + d] = s;
    } else if (idx < DM * E2 + DM) {
        int d = idx - DM * E2;
        float s = fc1b[d];
        for (int i = 0; i < EE; i++) s = fmaf(fc1w[d * FC1K + i], g_co[i], s);
        g_cvalid[d] = s;
    } else if (idx < DM * E2 + DM + DM * DM) {
        int r = idx - (DM * E2 + DM);
        int d = r / DM, s2 = r - d * DM;
        g_gsrcT[s2 * DM + d] = fc1w[d * FC1K + EE + s2];
    } else if (idx < DM * E2 + DM + 2 * DM * DM) {
        int r = idx - (DM * E2 + DM + DM * DM);
        int d = r / DM, k = r - d * DM;
        g_fc2T[k * DM + d] = fc2w[d * DM + k];
    }
}

// ---------------- K1: time-feat + qk + attention + mctx ----------------
// 16 batch rows / block, 288 threads, 3 blocks/SM.
#define K1_SMEM ((16*DM + 16*E2 + 16*2*NM + 16*NM + 16*NM + 2*TT) * 4)

__global__ void __launch_bounds__(288, 3)
k1_attn(const float* __restrict__ msg, const float* __restrict__ timeb,
        const float* __restrict__ tw, const float* __restrict__ tb) {
    extern __shared__ float sm[];
    float* src   = sm;                  // [16][172]
    float* qk    = src + 16 * DM;       // [16][544]
    float* attn  = qk + 16 * E2;        // [32][20]  (scores then attn)
    float* timev = attn + 16 * 2 * NM;  // [16][20]
    float* dls   = timev + 16 * NM;     // [16][20]  delta times
    float* twb   = dls + 16 * NM;       // [200]
    const int tid = threadIdx.x;
    const int b0 = blockIdx.x * 16;

    for (int i = tid; i < 2 * TT; i += 288) twb[i] = (i < TT) ? tw[i] : tb[i - TT];
    for (int i = tid; i < 16 * NM; i += 288)
        timev[i] = timeb[(b0 + i / NM) * NM + (i % NM)];
    __syncthreads();

    if (tid < 16) {
        bool all_neg = true;
        float t_last = timev[tid * NM + NM - 1];
        for (int n = 0; n < NM; n++) {
            float tv = timev[tid * NM + n];
            all_neg = all_neg && (tv < 0.0f);
            dls[tid * NM + n] = tv - t_last;
        }
        g_inv[b0 + tid] = (unsigned char)all_neg;
    }
    // src rows (last message per batch), float4 vectorized
    for (int i = tid; i < 16 * DMV; i += 288) {
        int b = i / DMV, dv = i - b * DMV;
        ((float4*)src)[b * DMV + dv] =
            ((const float4*)msg)[((size_t)(b0 + b) * NM + NM - 1) * DMV + dv];
    }
    __syncthreads();

    // ---- qk[b][e2] = Aqk @ src + cqk : 2D register tile (4 e2 x 8 b) ----
    if (tid < 272) {
        const int eg = tid % 136;          // e2 = eg*4 .. +3
        const int bg = (tid / 136) * 8;    // batch base 0 or 8
        float4 acc[8];
#pragma unroll
        for (int b = 0; b < 8; b++) acc[b] = make_float4(0.f, 0.f, 0.f, 0.f);
        const float4* W = (const float4*)g_aqkT;
#pragma unroll 4
        for (int k = 0; k < DM; k++) {
            float4 w = W[k * E2V + eg];
#pragma unroll
            for (int b = 0; b < 8; b++) {
                float a = src[(bg + b) * DM + k];
                acc[b].x = fmaf(w.x, a, acc[b].x);
                acc[b].y = fmaf(w.y, a, acc[b].y);
                acc[b].z = fmaf(w.z, a, acc[b].z);
                acc[b].w = fmaf(w.w, a, acc[b].w);
            }
        }
        float4 c = ((const float4*)g_cqk)[eg];
#pragma unroll
        for (int b = 0; b < 8; b++) {
            float4 v;
            v.x = acc[b].x + c.x; v.y = acc[b].y + c.y;
            v.z = acc[b].z + c.z; v.w = acc[b].w + c.w;
            ((float4*)qk)[(bg + b) * E2V + eg] = v;
        }
    }
    __syncthreads();

    // ---- scores: warp per 2 batch rows, time features recomputed ----
    const int w = tid >> 5, lane = tid & 31;
    if (w < 8) {
        for (int bbr = 0; bbr < 2; bbr++) {
            int bi = w * 2 + bbr;
            const float* qk0 = qk + bi * E2;
            const float* qk1 = qk0 + EE;
            for (int n = 0; n < NM; n++) {
                float s0 = 0.f, s1 = 0.f;
                const float* mrow = msg + ((size_t)(b0 + bi) * NM + n) * DM;
                for (int d = lane; d < DM; d += 32) {
                    float m = mrow[d];
                    s0 = fmaf(qk0[d], m, s0);
                    s1 = fmaf(qk1[d], m, s1);
                }
                float dl = dls[bi * NM + n];
                for (int t = lane; t < TT; t += 32) {
                    float f = __cosf(fmaf(dl, twb[t], twb[TT + t]));
                    s0 = fmaf(qk0[DM + t], f, s0);
                    s1 = fmaf(qk1[DM + t], f, s1);
                }
#pragma unroll
                for (int off = 16; off; off >>= 1) {
                    s0 += __shfl_xor_sync(0xffffffffu, s0, off);
                    s1 += __shfl_xor_sync(0xffffffffu, s1, off);
                }
                if (lane == 0) {
                    bool mk = timev[bi * NM + n] < 0.0f;
                    attn[(bi * 2) * NM + n]     = mk ? -1e9f : s0;
                    attn[(bi * 2 + 1) * NM + n] = mk ? -1e9f : s1;
                }
            }
        }
    }
    __syncthreads();

    // ---- softmax: one thread per (b,h) ----
    if (tid < 32) {
        float* row = attn + tid * NM;
        float mx = -3.4e38f;
        for (int n = 0; n < NM; n++) mx = fmaxf(mx, row[n]);
        float sum = 0.f;
        for (int n = 0; n < NM; n++) { float e = __expf(row[n] - mx); row[n] = e; sum += e; }
        float r = 1.0f / sum;
        for (int n = 0; n < NM; n++) row[n] *= r;
    }
    __syncthreads();

    // ---- mctx[b][e2] = sum_n attn * msgs  (time part recomputes cos) ----
    if (tid < EE) {
        float a0[16], a1[16];
#pragma unroll
        for (int t = 0; t < 16; t++) { a0[t] = 0.f; a1[t] = 0.f; }
        if (tid < DM) {
            for (int n = 0; n < NM; n++) {
#pragma unroll
                for (int b = 0; b < 16; b++) {
                    float m = msg[((size_t)(b0 + b) * NM + n) * DM + tid];
                    a0[b] = fmaf(attn[(b * 2) * NM + n], m, a0[b]);
                    a1[b] = fmaf(attn[(b * 2 + 1) * NM + n], m, a1[b]);
                }
            }
        } else {
            int t0 = tid - DM;
            float wt = twb[t0], bt = twb[TT + t0];
            for (int n = 0; n < NM; n++) {
#pragma unroll
                for (int b = 0; b < 16; b++) {
                    float f = __cosf(fmaf(dls[b * NM + n], wt, bt));
                    a0[b] = fmaf(attn[(b * 2) * NM + n], f, a0[b]);
                    a1[b] = fmaf(attn[(b * 2 + 1) * NM + n], f, a1[b]);
                }
            }
        }
#pragma unroll
        for (int b = 0; b < 16; b++) {
            g_mctx[(size_t)(b0 + b) * E2 + tid]      = a0[b];
            g_mctx[(size_t)(b0 + b) * E2 + EE + tid] = a1[b];
        }
    }
}

// ---------------- K2: fused out_proj+fc1 -> relu -> fc2 ----------------
// 16 batches/block, 192 threads = 48 d-groups x 4 batch-groups.
#define K2_SMEM ((16*E2 + 16*DM + 16*DM) * 4 + 64)

__global__ void __launch_bounds__(192, 3)
k2_out(const float* __restrict__ msg, const float* __restrict__ fc1b,
       const float* __restrict__ fc2b, float* __restrict__ out) {
    extern __shared__ float sm[];
    float* mctx = sm;               // [16][544]
    float* src  = mctx + 16 * E2;   // [16][172]
    float* hbuf = src + 16 * DM;    // [16][172]
    int*   inv  = (int*)(hbuf + 16 * DM);
    const int tid = threadIdx.x;
    const int b0 = blockIdx.x * 16;

    if (tid < 16) inv[tid] = (int)g_inv[b0 + tid];
    __syncthreads();
    {
        const float4 z4 = make_float4(0.f, 0.f, 0.f, 0.f);
        for (int i = tid; i < 16 * E2V; i += 192) {
            int b = i / E2V;
            float4 v = ((const float4*)g_mctx)[(size_t)(b0 + b) * E2V + (i - b * E2V)];
            ((float4*)mctx)[i] = inv[b] ? z4 : v;
        }
        for (int i = tid; i < 16 * DMV; i += 192) {
            int b = i / DMV;
            ((float4*)src)[i] =
                ((const float4*)msg)[((size_t)(b0 + b) * NM + NM - 1) * DMV + (i - b * DMV)];
        }
    }
    __syncthreads();

    const int dg = tid % 48;          // d = dg*4 .. +3 (valid when dg < 43)
    const int bg = (tid / 48) * 4;    // batch base: 0,4,8,12
    const bool act = dg < DMV;

    if (act) {
        float4 acc[4];
        {
            float4 cv = ((const float4*)g_cvalid)[dg];
            float4 fb = ((const float4*)fc1b)[dg];
#pragma unroll
            for (int b = 0; b < 4; b++) acc[b] = inv[bg + b] ? fb : cv;
        }
        const float4* WG = (const float4*)g_GT;
#pragma unroll 4
        for (int k = 0; k < E2; k++) {
            float4 w = WG[k * DMV + dg];
#pragma unroll
            for (int b = 0; b < 4; b++) {
                float a = mctx[(bg + b) * E2 + k];
                acc[b].x = fmaf(w.x, a, acc[b].x);
                acc[b].y = fmaf(w.y, a, acc[b].y);
                acc[b].z = fmaf(w.z, a, acc[b].z);
                acc[b].w = fmaf(w.w, a, acc[b].w);
            }
        }
        const float4* WS = (const float4*)g_gsrcT;
#pragma unroll 4
        for (int k = 0; k < DM; k++) {
            float4 w = WS[k * DMV + dg];
#pragma unroll
            for (int b = 0; b < 4; b++) {
                float a = src[(bg + b) * DM + k];
                acc[b].x = fmaf(w.x, a, acc[b].x);
                acc[b].y = fmaf(w.y, a, acc[b].y);
                acc[b].z = fmaf(w.z, a, acc[b].z);
                acc[b].w = fmaf(w.w, a, acc[b].w);
            }
        }
#pragma unroll
        for (int b = 0; b < 4; b++) {
            float4 r;
            r.x = fmaxf(acc[b].x, 0.f); r.y = fmaxf(acc[b].y, 0.f);
            r.z = fmaxf(acc[b].z, 0.f); r.w = fmaxf(acc[b].w, 0.f);
            ((float4*)hbuf)[(bg + b) * DMV + dg] = r;
        }
    }
    __syncthreads();

    if (act) {
        float4 acc[4];
        {
            float4 fb = ((const float4*)fc2b)[dg];
#pragma unroll
            for (int b = 0; b < 4; b++) acc[b] = fb;
        }
        const float4* WF = (const float4*)g_fc2T;
#pragma unroll 4
        for (int k = 0; k < DM; k++) {
            float4 w = WF[k * DMV + dg];
#pragma unroll
            for (int b = 0; b < 4; b++) {
                float a = hbuf[(bg + b) * DM + k];
                acc[b].x = fmaf(w.x, a, acc[b].x);
                acc[b].y = fmaf(w.y, a, acc[b].y);
                acc[b].z = fmaf(w.z, a, acc[b].z);
                acc[b].w = fmaf(w.w, a, acc[b].w);
            }
        }
#pragma unroll
        for (int b = 0; b < 4; b++)
            ((float4*)out)[(size_t)(b0 + bg + b) * DMV + dg] = acc[b];
    }
}

// ---------------- launch ----------------
extern "C" void kernel_launch(void* const* d_in, const int* in_sizes, int n_in,
                              void* d_out, int out_size) {
    const float* msg   = (const float*)d_in[0];   // (B,N,D)
    const float* timeb = (const float*)d_in[1];   // (B,N)
    // d_in[2] = memory (unused by reference)
    const float* tw    = (const float*)d_in[3];   // (T,)
    const float* tb    = (const float*)d_in[4];   // (T,)
    const float* ipw   = (const float*)d_in[5];   // (3E,E)
    const float* ipb   = (const float*)d_in[6];   // (3E,)
    const float* opw   = (const float*)d_in[7];   // (E,E)
    const float* opb   = (const float*)d_in[8];   // (E,)
    const float* fc1w  = (const float*)d_in[9];   // (D,E+D)
    const float* fc1b  = (const float*)d_in[10];  // (D,)
    const float* fc2w  = (const float*)d_in[11];  // (D,D)
    const float* fc2b  = (const float*)d_in[12];  // (D,)
    float* out = (float*)d_out;

    cudaFuncSetAttribute(k1_attn, cudaFuncAttributeMaxDynamicSharedMemorySize, K1_SMEM);
    cudaFuncSetAttribute(k2_out,  cudaFuncAttributeMaxDynamicSharedMemorySize, K2_SMEM);

    prep_qv<<<2, 256>>>(ipw, ipb, tb);
    prep_wf<<<(2 * EE * EE + EE + 255) / 256, 256>>>(ipw, ipb, opw, opb);
    prep_aqk<<<(DM * E2 + E2 + 255) / 256, 256>>>(ipw);
    prep_g<<<(DM * E2 + DM + 2 * DM * DM + 255) / 256, 256>>>(fc1w, fc1b, fc2w);

    k1_attn<<<BB / 16, 288, K1_SMEM>>>(msg, timeb, tw, tb);
    k2_out<<<BB / 16, 192, K2_SMEM>>>(msg, fc1b, fc2b, out);
}

// round 7
// speedup vs baseline: 1.9423x; 1.0012x over previous
#include <cuda_runtime.h>
#include <cuda_bf16.h>
#include <math.h>

// Problem constants
#define BB   32768
#define NM   20
#define DM   172      // message dim
#define TT   100      // time feature dim
#define EE   272      // E = D + T
#define HD_  136
#define E2   544      // H * E (also 2E)
#define E2V  136      // E2/4
#define DMV  43       // DM/4
#define FC1K 444      // E + D

__device__ __constant__ float kSCALE = 0.08574929257125442f; // 1/sqrt(136)

// ---------------- device scratch (static, no runtime alloc) ----------------
__device__ float g_qv[EE];                 // wq time-part @ cos(time_b) + bq
__device__ float g_wf[2 * EE * EE];        // Wf_h = out_proj[:,h] @ wv_h
__device__ float g_co[EE];                 // out_proj @ bv + out_b
__device__ float g_aqkT[DM * E2];          // [d][e2] e2 = h*272+e  (pre-scaled)
__device__ float g_cqk[E2];                // per-e2 const (pre-scaled)
__device__ float g_GT[E2 * DM];            // [k][d]
__device__ float g_cvalid[DM];             // fc1[:, :E]@co + fc1_b
__device__ float g_gsrcT[DM * DM];         // [s][d] = fc1_w[d][E+s]
__device__ float g_fc2T[DM * DM];          // [k][d]
__device__ float g_mctx[(size_t)BB * E2];  // attn-weighted msgs, [b][e2]
__device__ unsigned char g_inv[BB];

// ---------------- precompute: stage 1 (qv + wf + co) ----------------
#define P1_TOT (EE + 2 * EE * EE + EE)
__global__ void prep1(const float* __restrict__ ipw, const float* __restrict__ ipb,
                      const float* __restrict__ tb,
                      const float* __restrict__ opw, const float* __restrict__ opb) {
    int idx = blockIdx.x * blockDim.x + threadIdx.x;
    if (idx < EE) {
        int r = idx;
        float s = ipb[r];
        for (int t = 0; t < TT; t++) s = fmaf(ipw[r * EE + DM + t], cosf(tb[t]), s);
        g_qv[r] = s;
    } else if (idx < EE + 2 * EE * EE) {
        int q = idx - EE;
        int h = q / (EE * EE);
        int r = q - h * EE * EE;
        int i = r / EE, e = r - (r / EE) * EE;
        float s = 0.f;
        for (int j = 0; j < HD_; j++)
            s = fmaf(opw[i * EE + h * HD_ + j], ipw[(2 * EE + h * HD_ + j) * EE + e], s);
        g_wf[q] = s;
    } else if (idx < P1_TOT) {
        int i = idx - EE - 2 * EE * EE;
        float s = opb[i];
        for (int k = 0; k < EE; k++) s = fmaf(opw[i * EE + k], ipb[2 * EE + k], s);
        g_co[i] = s;
    }
}

// ---------------- precompute: stage 2 (aqk, cqk, G, cvalid, transposes) ----
#define P2_TOT (DM * E2 + E2 + DM * E2 + DM + 2 * DM * DM)
__global__ void prep2(const float* __restrict__ ipw,
                      const float* __restrict__ fc1w, const float* __restrict__ fc1b,
                      const float* __restrict__ fc2w) {
    int idx = blockIdx.x * blockDim.x + threadIdx.x;
    if (idx < DM * E2) {
        int d = idx / E2, e2 = idx - d * E2;
        int h = e2 / EE, e = e2 - h * EE;
        float s = 0.f;
        for (int j = 0; j < HD_; j++)
            s = fmaf(ipw[(EE + h * HD_ + j) * EE + e], ipw[(h * HD_ + j) * EE + d], s);
        g_aqkT[idx] = s * kSCALE;
    } else if (idx < DM * E2 + E2) {
        int e2 = idx - DM * E2;
        int h = e2 / EE, e = e2 - h * EE;
        float s = 0.f;
        for (int j = 0; j < HD_; j++)
            s = fmaf(ipw[(EE + h * HD_ + j) * EE + e], g_qv[h * HD_ + j], s);
        g_cqk[e2] = s * kSCALE;
    } else if (idx < DM * E2 + E2 + DM * E2) {
        int r = idx - (DM * E2 + E2);
        int d = r / E2, e2 = r - d * E2;
        int h = e2 / EE, e = e2 - h * EE;
        float s = 0.f;
        for (int i = 0; i < EE; i++)
            s = fmaf(fc1w[d * FC1K + i], g_wf[(h * EE + i) * EE + e], s);
        g_GT[e2 * DM + d] = s;
    } else if (idx < DM * E2 + E2 + DM * E2 + DM) {
        int d = idx - (DM * E2 + E2 + DM * E2);
        float s = fc1b[d];
        for (int i = 0; i < EE; i++) s = fmaf(fc1w[d * FC1K + i], g_co[i], s);
        g_cvalid[d] = s;
    } else if (idx < DM * E2 + E2 + DM * E2 + DM + DM * DM) {
        int r = idx - (DM * E2 + E2 + DM * E2 + DM);
        int d = r / DM, s2 = r - d * DM;
        g_gsrcT[s2 * DM + d] = fc1w[d * FC1K + EE + s2];
    } else if (idx < P2_TOT) {
        int r = idx - (DM * E2 + E2 + DM * E2 + DM + DM * DM);
        int d = r / DM, k = r - d * DM;
        g_fc2T[k * DM + d] = fc2w[d * DM + k];
    }
}

// ---------------- K1: time-feat + qk + attention + mctx ----------------
// 16 batch rows / block, 288 threads, 3 blocks/SM.
#define K1_SMEM ((16*DM + 16*E2 + 16*2*NM + 16*NM + 16*NM + 2*TT) * 4)

__global__ void __launch_bounds__(288, 3)
k1_attn(const float* __restrict__ msg, const float* __restrict__ timeb,
        const float* __restrict__ tw, const float* __restrict__ tb) {
    extern __shared__ float sm[];
    float* src   = sm;                  // [16][172]
    float* qk    = src + 16 * DM;       // [16][544]
    float* attn  = qk + 16 * E2;        // [32][20]  (scores then attn)
    float* timev = attn + 16 * 2 * NM;  // [16][20]
    float* dls   = timev + 16 * NM;     // [16][20]  delta times
    float* twb   = dls + 16 * NM;       // [200]
    const int tid = threadIdx.x;
    const int b0 = blockIdx.x * 16;

    for (int i = tid; i < 2 * TT; i += 288) twb[i] = (i < TT) ? tw[i] : tb[i - TT];
    for (int i = tid; i < 16 * NM; i += 288)
        timev[i] = timeb[(b0 + i / NM) * NM + (i % NM)];
    __syncthreads();

    if (tid < 16) {
        bool all_neg = true;
        float t_last = timev[tid * NM + NM - 1];
        for (int n = 0; n < NM; n++) {
            float tv = timev[tid * NM + n];
            all_neg = all_neg && (tv < 0.0f);
            dls[tid * NM + n] = tv - t_last;
        }
        g_inv[b0 + tid] = (unsigned char)all_neg;
    }
    // src rows (last message per batch), float4 vectorized
    for (int i = tid; i < 16 * DMV; i += 288) {
        int b = i / DMV, dv = i - b * DMV;
        ((float4*)src)[b * DMV + dv] =
            ((const float4*)msg)[((size_t)(b0 + b) * NM + NM - 1) * DMV + dv];
    }
    __syncthreads();

    // ---- qk[b][e2] = Aqk @ src + cqk : 2D register tile (4 e2 x 8 b) ----
    if (tid < 272) {
        const int eg = tid % 136;          // e2 = eg*4 .. +3
        const int bg = (tid / 136) * 8;    // batch base 0 or 8
        float4 acc[8];
#pragma unroll
        for (int b = 0; b < 8; b++) acc[b] = make_float4(0.f, 0.f, 0.f, 0.f);
        const float4* W = (const float4*)g_aqkT;
        float4 w = W[eg];
#pragma unroll 4
        for (int k = 0; k < DM; k++) {
            float4 wn = (k + 1 < DM) ? W[(k + 1) * E2V + eg] : make_float4(0.f,0.f,0.f,0.f);
#pragma unroll
            for (int b = 0; b < 8; b++) {
                float a = src[(bg + b) * DM + k];
                acc[b].x = fmaf(w.x, a, acc[b].x);
                acc[b].y = fmaf(w.y, a, acc[b].y);
                acc[b].z = fmaf(w.z, a, acc[b].z);
                acc[b].w = fmaf(w.w, a, acc[b].w);
            }
            w = wn;
        }
        float4 c = ((const float4*)g_cqk)[eg];
#pragma unroll
        for (int b = 0; b < 8; b++) {
            float4 v;
            v.x = acc[b].x + c.x; v.y = acc[b].y + c.y;
            v.z = acc[b].z + c.z; v.w = acc[b].w + c.w;
            ((float4*)qk)[(bg + b) * E2V + eg] = v;
        }
    }
    __syncthreads();

    // ---- scores: warp per 2 batch rows, time features recomputed ----
    const int w = tid >> 5, lane = tid & 31;
    if (w < 8) {
        for (int bbr = 0; bbr < 2; bbr++) {
            int bi = w * 2 + bbr;
            const float* qk0 = qk + bi * E2;
            const float* qk1 = qk0 + EE;
            for (int n = 0; n < NM; n++) {
                float s0 = 0.f, s1 = 0.f;
                const float* mrow = msg + ((size_t)(b0 + bi) * NM + n) * DM;
                for (int d = lane; d < DM; d += 32) {
                    float m = mrow[d];
                    s0 = fmaf(qk0[d], m, s0);
                    s1 = fmaf(qk1[d], m, s1);
                }
                float dl = dls[bi * NM + n];
                for (int t = lane; t < TT; t += 32) {
                    float f = __cosf(fmaf(dl, twb[t], twb[TT + t]));
                    s0 = fmaf(qk0[DM + t], f, s0);
                    s1 = fmaf(qk1[DM + t], f, s1);
                }
#pragma unroll
                for (int off = 16; off; off >>= 1) {
                    s0 += __shfl_xor_sync(0xffffffffu, s0, off);
                    s1 += __shfl_xor_sync(0xffffffffu, s1, off);
                }
                if (lane == 0) {
                    bool mk = timev[bi * NM + n] < 0.0f;
                    attn[(bi * 2) * NM + n]     = mk ? -1e9f : s0;
                    attn[(bi * 2 + 1) * NM + n] = mk ? -1e9f : s1;
                }
            }
        }
    }
    __syncthreads();

    // ---- softmax: one thread per (b,h) ----
    if (tid < 32) {
        float* row = attn + tid * NM;
        float mx = -3.4e38f;
        for (int n = 0; n < NM; n++) mx = fmaxf(mx, row[n]);
        float sum = 0.f;
        for (int n = 0; n < NM; n++) { float e = __expf(row[n] - mx); row[n] = e; sum += e; }
        float r = 1.0f / sum;
        for (int n = 0; n < NM; n++) row[n] *= r;
    }
    __syncthreads();

    // ---- mctx[b][e2] = sum_n attn * msgs  (time part recomputes cos) ----
    if (tid < EE) {
        float a0[16], a1[16];
#pragma unroll
        for (int t = 0; t < 16; t++) { a0[t] = 0.f; a1[t] = 0.f; }
        if (tid < DM) {
            for (int n = 0; n < NM; n++) {
#pragma unroll
                for (int b = 0; b < 16; b++) {
                    float m = msg[((size_t)(b0 + b) * NM + n) * DM + tid];
                    a0[b] = fmaf(attn[(b * 2) * NM + n], m, a0[b]);
                    a1[b] = fmaf(attn[(b * 2 + 1) * NM + n], m, a1[b]);
                }
            }
        } else {
            int t0 = tid - DM;
            float wt = twb[t0], bt = twb[TT + t0];
            for (int n = 0; n < NM; n++) {
#pragma unroll
                for (int b = 0; b < 16; b++) {
                    float f = __cosf(fmaf(dls[b * NM + n], wt, bt));
                    a0[b] = fmaf(attn[(b * 2) * NM + n], f, a0[b]);
                    a1[b] = fmaf(attn[(b * 2 + 1) * NM + n], f, a1[b]);
                }
            }
        }
#pragma unroll
        for (int b = 0; b < 16; b++) {
            g_mctx[(size_t)(b0 + b) * E2 + tid]      = a0[b];
            g_mctx[(size_t)(b0 + b) * E2 + EE + tid] = a1[b];
        }
    }
}

// ---------------- K2: fused out_proj+fc1 -> relu -> fc2 ----------------
// 16 batches/block, 192 threads = 48 d-groups x 4 batch-groups, 4 blocks/SM.
// hbuf overlays mctx (mctx fully consumed before hbuf written).
#define K2_SMEM ((16*E2 + 16*DM) * 4 + 64)

__global__ void __launch_bounds__(192, 4)
k2_out(const float* __restrict__ msg, const float* __restrict__ fc1b,
       const float* __restrict__ fc2b, float* __restrict__ out) {
    extern __shared__ float sm[];
    float* mctx = sm;               // [16][544]
    float* src  = mctx + 16 * E2;   // [16][172]
    float* hbuf = mctx;             // overlay: [16][172], written after GT/gsrc done
    int*   inv  = (int*)(src + 16 * DM);
    const int tid = threadIdx.x;
    const int b0 = blockIdx.x * 16;

    if (tid < 16) inv[tid] = (int)g_inv[b0 + tid];
    __syncthreads();
    {
        const float4 z4 = make_float4(0.f, 0.f, 0.f, 0.f);
        for (int i = tid; i < 16 * E2V; i += 192) {
            int b = i / E2V;
            float4 v = ((const float4*)g_mctx)[(size_t)(b0 + b) * E2V + (i - b * E2V)];
            ((float4*)mctx)[i] = inv[b] ? z4 : v;
        }
        for (int i = tid; i < 16 * DMV; i += 192) {
            int b = i / DMV;
            ((float4*)src)[i] =
                ((const float4*)msg)[((size_t)(b0 + b) * NM + NM - 1) * DMV + (i - b * DMV)];
        }
    }
    __syncthreads();

    const int dg = tid % 48;          // d = dg*4 .. +3 (valid when dg < 43)
    const int bg = (tid / 48) * 4;    // batch base: 0,4,8,12
    const bool act = dg < DMV;

    float4 acc[4];
    if (act) {
        {
            float4 cv = ((const float4*)g_cvalid)[dg];
            float4 fb = ((const float4*)fc1b)[dg];
#pragma unroll
            for (int b = 0; b < 4; b++) acc[b] = inv[bg + b] ? fb : cv;
        }
        const float4* WG = (const float4*)g_GT;
        float4 w = WG[dg];
#pragma unroll 4
        for (int k = 0; k < E2; k++) {
            float4 wn = (k + 1 < E2) ? WG[(k + 1) * DMV + dg] : make_float4(0.f,0.f,0.f,0.f);
#pragma unroll
            for (int b = 0; b < 4; b++) {
                float a = mctx[(bg + b) * E2 + k];
                acc[b].x = fmaf(w.x, a, acc[b].x);
                acc[b].y = fmaf(w.y, a, acc[b].y);
                acc[b].z = fmaf(w.z, a, acc[b].z);
                acc[b].w = fmaf(w.w, a, acc[b].w);
            }
            w = wn;
        }
        const float4* WS = (const float4*)g_gsrcT;
        w = WS[dg];
#pragma unroll 4
        for (int k = 0; k < DM; k++) {
            float4 wn = (k + 1 < DM) ? WS[(k + 1) * DMV + dg] : make_float4(0.f,0.f,0.f,0.f);
#pragma unroll
            for (int b = 0; b < 4; b++) {
                float a = src[(bg + b) * DM + k];
                acc[b].x = fmaf(w.x, a, acc[b].x);
                acc[b].y = fmaf(w.y, a, acc[b].y);
                acc[b].z = fmaf(w.z, a, acc[b].z);
                acc[b].w = fmaf(w.w, a, acc[b].w);
            }
            w = wn;
        }
    }
    __syncthreads();   // everyone finished READING mctx
    if (act) {
#pragma unroll
        for (int b = 0; b < 4; b++) {
            float4 r;
            r.x = fmaxf(acc[b].x, 0.f); r.y = fmaxf(acc[b].y, 0.f);
            r.z = fmaxf(acc[b].z, 0.f); r.w = fmaxf(acc[b].w, 0.f);
            ((float4*)hbuf)[(bg + b) * DMV + dg] = r;
        }
    }
    __syncthreads();

    if (act) {
        {
            float4 fb = ((const float4*)fc2b)[dg];
#pragma unroll
            for (int b = 0; b < 4; b++) acc[b] = fb;
        }
        const float4* WF = (const float4*)g_fc2T;
        float4 w = WF[dg];
#pragma unroll 4
        for (int k = 0; k < DM; k++) {
            float4 wn = (k + 1 < DM) ? WF[(k + 1) * DMV + dg] : make_float4(0.f,0.f,0.f,0.f);
#pragma unroll
            for (int b = 0; b < 4; b++) {
                float a = hbuf[(bg + b) * DM + k];
                acc[b].x = fmaf(w.x, a, acc[b].x);
                acc[b].y = fmaf(w.y, a, acc[b].y);
                acc[b].z = fmaf(w.z, a, acc[b].z);
                acc[b].w = fmaf(w.w, a, acc[b].w);
            }
            w = wn;
        }
#pragma unroll
        for (int b = 0; b < 4; b++)
            ((float4*)out)[(size_t)(b0 + bg + b) * DMV + dg] = acc[b];
    }
}

// ---------------- launch ----------------
extern "C" void kernel_launch(void* const* d_in, const int* in_sizes, int n_in,
                              void* d_out, int out_size) {
    const float* msg   = (const float*)d_in[0];   // (B,N,D)
    const float* timeb = (const float*)d_in[1];   // (B,N)
    // d_in[2] = memory (unused by reference)
    const float* tw    = (const float*)d_in[3];   // (T,)
    const float* tb    = (const float*)d_in[4];   // (T,)
    const float* ipw   = (const float*)d_in[5];   // (3E,E)
    const float* ipb   = (const float*)d_in[6];   // (3E,)
    const float* opw   = (const float*)d_in[7];   // (E,E)
    const float* opb   = (const float*)d_in[8];   // (E,)
    const float* fc1w  = (const float*)d_in[9];   // (D,E+D)
    const float* fc1b  = (const float*)d_in[10];  // (D,)
    const float* fc2w  = (const float*)d_in[11];  // (D,D)
    const float* fc2b  = (const float*)d_in[12];  // (D,)
    float* out = (float*)d_out;

    cudaFuncSetAttribute(k1_attn, cudaFuncAttributeMaxDynamicSharedMemorySize, K1_SMEM);
    cudaFuncSetAttribute(k2_out,  cudaFuncAttributeMaxDynamicSharedMemorySize, K2_SMEM);

    prep1<<<(P1_TOT + 255) / 256, 256>>>(ipw, ipb, tb, opw, opb);
    prep2<<<(P2_TOT + 255) / 256, 256>>>(ipw, fc1w, fc1b, fc2w);

    k1_attn<<<BB / 16, 288, K1_SMEM>>>(msg, timeb, tw, tb);
    k2_out<<<BB / 16, 192, K2_SMEM>>>(msg, fc1b, fc2b, out);
}

// round 10
// speedup vs baseline: 2.3846x; 1.2277x over previous
#include <cuda_runtime.h>
#include <cuda_bf16.h>
#include <math.h>

// Problem constants
#define BB   32768
#define NM   20
#define DM   172      // message dim
#define TT   100      // time feature dim
#define EE   272      // E = D + T
#define EEV  68       // EE/4
#define HD_  136
#define E2   544      // H * E (also 2E)
#define E2V  136      // E2/4
#define DMV  43       // DM/4
#define FC1K 444      // E + D

__device__ __constant__ float kSCALE = 0.08574929257125442f; // 1/sqrt(136)

// ---------------- device scratch (static, no runtime alloc) ----------------
__device__ float g_qv[EE];                 // wq time-part @ cos(time_b) + bq
__device__ float g_wf[2 * EE * EE];        // Wf_h = out_proj[:,h] @ wv_h
__device__ float g_co[EE];                 // out_proj @ bv + out_b
__device__ float g_aqkT[DM * E2];          // [d][e2] e2 = h*272+e  (pre-scaled)
__device__ float g_cqk[E2];                // per-e2 const (pre-scaled)
__device__ float g_GT[E2 * DM];            // [k][d]
__device__ float g_cvalid[DM];             // fc1[:, :E]@co + fc1_b
__device__ float g_gsrcT[DM * DM];         // [s][d] = fc1_w[d][E+s]
__device__ float g_fc2T[DM * DM];          // [k][d]

// ---------------- precompute: stage 1 (qv + wf + co) ----------------
#define P1_TOT (EE + 2 * EE * EE + EE)
__global__ void prep1(const float* __restrict__ ipw, const float* __restrict__ ipb,
                      const float* __restrict__ tb,
                      const float* __restrict__ opw, const float* __restrict__ opb) {
    int idx = blockIdx.x * blockDim.x + threadIdx.x;
    if (idx < EE) {
        int r = idx;
        float s = ipb[r];
        for (int t = 0; t < TT; t++) s = fmaf(ipw[r * EE + DM + t], cosf(tb[t]), s);
        g_qv[r] = s;
    } else if (idx < EE + 2 * EE * EE) {
        int q = idx - EE;
        int h = q / (EE * EE);
        int r = q - h * EE * EE;
        int i = r / EE, e = r - (r / EE) * EE;
        float s = 0.f;
        for (int j = 0; j < HD_; j++)
            s = fmaf(opw[i * EE + h * HD_ + j], ipw[(2 * EE + h * HD_ + j) * EE + e], s);
        g_wf[q] = s;
    } else if (idx < P1_TOT) {
        int i = idx - EE - 2 * EE * EE;
        float s = opb[i];
        for (int k = 0; k < EE; k++) s = fmaf(opw[i * EE + k], ipb[2 * EE + k], s);
        g_co[i] = s;
    }
}

// ---------------- precompute: stage 2 (aqk, cqk, G, cvalid, transposes) ----
#define P2_TOT (DM * E2 + E2 + DM * E2 + DM + 2 * DM * DM)
__global__ void prep2(const float* __restrict__ ipw,
                      const float* __restrict__ fc1w, const float* __restrict__ fc1b,
                      const float* __restrict__ fc2w) {
    int idx = blockIdx.x * blockDim.x + threadIdx.x;
    if (idx < DM * E2) {
        int d = idx / E2, e2 = idx - d * E2;
        int h = e2 / EE, e = e2 - h * EE;
        float s = 0.f;
        for (int j = 0; j < HD_; j++)
            s = fmaf(ipw[(EE + h * HD_ + j) * EE + e], ipw[(h * HD_ + j) * EE + d], s);
        g_aqkT[idx] = s * kSCALE;
    } else if (idx < DM * E2 + E2) {
        int e2 = idx - DM * E2;
        int h = e2 / EE, e = e2 - h * EE;
        float s = 0.f;
        for (int j = 0; j < HD_; j++)
            s = fmaf(ipw[(EE + h * HD_ + j) * EE + e], g_qv[h * HD_ + j], s);
        g_cqk[e2] = s * kSCALE;
    } else if (idx < DM * E2 + E2 + DM * E2) {
        int r = idx - (DM * E2 + E2);
        int d = r / E2, e2 = r - d * E2;
        int h = e2 / EE, e = e2 - h * EE;
        float s = 0.f;
        for (int i = 0; i < EE; i++)
            s = fmaf(fc1w[d * FC1K + i], g_wf[(h * EE + i) * EE + e], s);
        g_GT[e2 * DM + d] = s;
    } else if (idx < DM * E2 + E2 + DM * E2 + DM) {
        int d = idx - (DM * E2 + E2 + DM * E2);
        float s = fc1b[d];
        for (int i = 0; i < EE; i++) s = fmaf(fc1w[d * FC1K + i], g_co[i], s);
        g_cvalid[d] = s;
    } else if (idx < DM * E2 + E2 + DM * E2 + DM + DM * DM) {
        int r = idx - (DM * E2 + E2 + DM * E2 + DM);
        int d = r / DM, s2 = r - d * DM;
        g_gsrcT[s2 * DM + d] = fc1w[d * FC1K + EE + s2];
    } else if (idx < P2_TOT) {
        int r = idx - (DM * E2 + E2 + DM * E2 + DM + DM * DM);
        int d = r / DM, k = r - d * DM;
        g_fc2T[k * DM + d] = fc2w[d * DM + k];
    }
}

// ---------------- fused kernel: attention + MLP, 16 batches/block ----------
// smem floats: src 2752 | mx(qk/mctx/hbuf) 8704 | attn 640 | timev 320
//              | dls 320 | twb 200 | inv 16
#define FS_SMEM ((16*DM + 16*E2 + 16*2*NM + 16*NM + 16*NM + 2*TT + 16) * 4)

__global__ void __launch_bounds__(288, 3)
fused(const float* __restrict__ msg, const float* __restrict__ timeb,
      const float* __restrict__ tw, const float* __restrict__ tb,
      const float* __restrict__ fc1b, const float* __restrict__ fc2b,
      float* __restrict__ out) {
    extern __shared__ float sm[];
    float* src   = sm;                  // [16][172]
    float* mx    = src + 16 * DM;       // [16][544]: qk -> mctx -> hbuf overlay
    float* attn  = mx + 16 * E2;        // [32][20]
    float* timev = attn + 16 * 2 * NM;  // [16][20]
    float* dls   = timev + 16 * NM;     // [16][20]
    float* twb   = dls + 16 * NM;       // [200]
    int*   inv   = (int*)(twb + 2 * TT);// [16]
    const int tid = threadIdx.x;
    const int b0 = blockIdx.x * 16;

    for (int i = tid; i < 2 * TT; i += 288) twb[i] = (i < TT) ? tw[i] : tb[i - TT];
    for (int i = tid; i < 16 * NM; i += 288)
        timev[i] = timeb[(b0 + i / NM) * NM + (i % NM)];
    __syncthreads();

    if (tid < 16) {
        bool all_neg = true;
        float t_last = timev[tid * NM + NM - 1];
        for (int n = 0; n < NM; n++) {
            float tv = timev[tid * NM + n];
            all_neg = all_neg && (tv < 0.0f);
            dls[tid * NM + n] = tv - t_last;
        }
        inv[tid] = (int)all_neg;
    }
    for (int i = tid; i < 16 * DMV; i += 288) {
        int b = i / DMV, dv = i - b * DMV;
        ((float4*)src)[b * DMV + dv] =
            ((const float4*)msg)[((size_t)(b0 + b) * NM + NM - 1) * DMV + dv];
    }
    __syncthreads();

    // ===== phase 1: qk[b][e2] = Aqk @ src + cqk (4-e2 x 8-b tile, k by 4) ====
    if (tid < 272) {
        const int eg = tid % 136;          // e2 group: columns eg*4..+3
        const int bg = (tid / 136) * 8;    // batch base 0 or 8
        float4 acc[8];
#pragma unroll
        for (int b = 0; b < 8; b++) acc[b] = make_float4(0.f, 0.f, 0.f, 0.f);
        const float4* W = (const float4*)g_aqkT;
        const float4* S = (const float4*)src;
        for (int kv = 0; kv < DMV; kv++) {
            const int k = kv * 4;
            float4 w0 = W[(k + 0) * E2V + eg];
            float4 w1 = W[(k + 1) * E2V + eg];
            float4 w2 = W[(k + 2) * E2V + eg];
            float4 w3 = W[(k + 3) * E2V + eg];
#pragma unroll
            for (int b = 0; b < 8; b++) {
                float4 s4 = S[(bg + b) * DMV + kv];
                acc[b].x = fmaf(w0.x, s4.x, acc[b].x);
                acc[b].y = fmaf(w0.y, s4.x, acc[b].y);
                acc[b].z = fmaf(w0.z, s4.x, acc[b].z);
                acc[b].w = fmaf(w0.w, s4.x, acc[b].w);
                acc[b].x = fmaf(w1.x, s4.y, acc[b].x);
                acc[b].y = fmaf(w1.y, s4.y, acc[b].y);
                acc[b].z = fmaf(w1.z, s4.y, acc[b].z);
                acc[b].w = fmaf(w1.w, s4.y, acc[b].w);
                acc[b].x = fmaf(w2.x, s4.z, acc[b].x);
                acc[b].y = fmaf(w2.y, s4.z, acc[b].y);
                acc[b].z = fmaf(w2.z, s4.z, acc[b].z);
                acc[b].w = fmaf(w2.w, s4.z, acc[b].w);
                acc[b].x = fmaf(w3.x, s4.w, acc[b].x);
                acc[b].y = fmaf(w3.y, s4.w, acc[b].y);
                acc[b].z = fmaf(w3.z, s4.w, acc[b].z);
                acc[b].w = fmaf(w3.w, s4.w, acc[b].w);
            }
        }
        float4 c = ((const float4*)g_cqk)[eg];
#pragma unroll
        for (int b = 0; b < 8; b++) {
            float4 v;
            v.x = acc[b].x + c.x; v.y = acc[b].y + c.y;
            v.z = acc[b].z + c.z; v.w = acc[b].w + c.w;
            ((float4*)mx)[(bg + b) * E2V + eg] = v;
        }
    }
    __syncthreads();

    // ===== phase 2: scores (warp per 2 batches), float4 msg/qk reads ========
    const int w = tid >> 5, lane = tid & 31;
    if (w < 8) {
        for (int bbr = 0; bbr < 2; bbr++) {
            int bi = w * 2 + bbr;
            const float*  qk0  = mx + bi * E2;
            const float*  qk1  = qk0 + EE;
            const float4* qk0v = (const float4*)qk0;
            const float4* qk1v = (const float4*)qk1;
            for (int n = 0; n < NM; n++) {
                float s0 = 0.f, s1 = 0.f;
                const float4* mrow4 =
                    (const float4*)(msg + ((size_t)(b0 + bi) * NM + n) * DM);
                for (int dv = lane; dv < DMV; dv += 32) {
                    float4 m = mrow4[dv];
                    float4 a = qk0v[dv];
                    float4 c = qk1v[dv];
                    s0 = fmaf(a.x, m.x, s0); s1 = fmaf(c.x, m.x, s1);
                    s0 = fmaf(a.y, m.y, s0); s1 = fmaf(c.y, m.y, s1);
                    s0 = fmaf(a.z, m.z, s0); s1 = fmaf(c.z, m.z, s1);
                    s0 = fmaf(a.w, m.w, s0); s1 = fmaf(c.w, m.w, s1);
                }
                float dl = dls[bi * NM + n];
                for (int t = lane; t < TT; t += 32) {
                    float f = __cosf(fmaf(dl, twb[t], twb[TT + t]));
                    s0 = fmaf(qk0[DM + t], f, s0);
                    s1 = fmaf(qk1[DM + t], f, s1);
                }
#pragma unroll
                for (int off = 16; off; off >>= 1) {
                    s0 += __shfl_xor_sync(0xffffffffu, s0, off);
                    s1 += __shfl_xor_sync(0xffffffffu, s1, off);
                }
                if (lane == 0) {
                    bool mk = timev[bi * NM + n] < 0.0f;
                    attn[(bi * 2) * NM + n]     = mk ? -1e9f : s0;
                    attn[(bi * 2 + 1) * NM + n] = mk ? -1e9f : s1;
                }
            }
        }
    }
    __syncthreads();

    // ===== phase 3: softmax, one thread per (b,h) ===========================
    if (tid < 32) {
        float* row = attn + tid * NM;
        float mxv = -3.4e38f;
        for (int n = 0; n < NM; n++) mxv = fmaxf(mxv, row[n]);
        float sum = 0.f;
        for (int n = 0; n < NM; n++) { float e = __expf(row[n] - mxv); row[n] = e; sum += e; }
        float r = 1.0f / sum;
        for (int n = 0; n < NM; n++) row[n] *= r;
    }
    __syncthreads();

    // ===== phase 4: mctx[b][e2] = sum_n attn*msgs, overwrite qk buffer ======
    // Uniform barriers: compute into registers -> barrier -> write -> barrier.
    {
        float a0[16], a1[16];
        if (tid < EE) {
#pragma unroll
            for (int t = 0; t < 16; t++) { a0[t] = 0.f; a1[t] = 0.f; }
            if (tid < DM) {
                for (int n = 0; n < NM; n++) {
#pragma unroll
                    for (int b = 0; b < 16; b++) {
                        float m = msg[((size_t)(b0 + b) * NM + n) * DM + tid];
                        a0[b] = fmaf(attn[(b * 2) * NM + n], m, a0[b]);
                        a1[b] = fmaf(attn[(b * 2 + 1) * NM + n], m, a1[b]);
                    }
                }
            } else {
                int t0 = tid - DM;
                float wt = twb[t0], bt = twb[TT + t0];
                for (int n = 0; n < NM; n++) {
#pragma unroll
                    for (int b = 0; b < 16; b++) {
                        float f = __cosf(fmaf(dls[b * NM + n], wt, bt));
                        a0[b] = fmaf(attn[(b * 2) * NM + n], f, a0[b]);
                        a1[b] = fmaf(attn[(b * 2 + 1) * NM + n], f, a1[b]);
                    }
                }
            }
        }
        __syncthreads();   // ALL threads: reads of qk buffer complete
        if (tid < EE) {
#pragma unroll
            for (int b = 0; b < 16; b++) {
                bool iv = inv[b] != 0;
                mx[b * E2 + tid]      = iv ? 0.f : a0[b];
                mx[b * E2 + EE + tid] = iv ? 0.f : a1[b];
            }
        }
    }
    __syncthreads();

    // ===== phase 5: h = relu(G@mctx + gsrc@src + c), 4-d x 4-b tile =========
    const int dg = tid % 48;          // d group (valid when < 43)
    const int bg = (tid / 48) * 4;    // batch base 0,4,8,12
    const bool act = (dg < DMV) && (tid < 192);

    float4 acc[4];
    if (act) {
        {
            float4 cv = ((const float4*)g_cvalid)[dg];
            float4 fb = ((const float4*)fc1b)[dg];
#pragma unroll
            for (int b = 0; b < 4; b++) acc[b] = inv[bg + b] ? fb : cv;
        }
        const float4* WG = (const float4*)g_GT;
        const float4* A  = (const float4*)mx;
        for (int kv = 0; kv < E2V; kv++) {
            const int k = kv * 4;
            float4 w0 = WG[(k + 0) * DMV + dg];
            float4 w1 = WG[(k + 1) * DMV + dg];
            float4 w2 = WG[(k + 2) * DMV + dg];
            float4 w3 = WG[(k + 3) * DMV + dg];
#pragma unroll
            for (int b = 0; b < 4; b++) {
                float4 a4 = A[(bg + b) * E2V + kv];
                acc[b].x = fmaf(w0.x, a4.x, acc[b].x);
                acc[b].y = fmaf(w0.y, a4.x, acc[b].y);
                acc[b].z = fmaf(w0.z, a4.x, acc[b].z);
                acc[b].w = fmaf(w0.w, a4.x, acc[b].w);
                acc[b].x = fmaf(w1.x, a4.y, acc[b].x);
                acc[b].y = fmaf(w1.y, a4.y, acc[b].y);
                acc[b].z = fmaf(w1.z, a4.y, acc[b].z);
                acc[b].w = fmaf(w1.w, a4.y, acc[b].w);
                acc[b].x = fmaf(w2.x, a4.z, acc[b].x);
                acc[b].y = fmaf(w2.y, a4.z, acc[b].y);
                acc[b].z = fmaf(w2.z, a4.z, acc[b].z);
                acc[b].w = fmaf(w2.w, a4.z, acc[b].w);
                acc[b].x = fmaf(w3.x, a4.w, acc[b].x);
                acc[b].y = fmaf(w3.y, a4.w, acc[b].y);
                acc[b].z = fmaf(w3.z, a4.w, acc[b].z);
                acc[b].w = fmaf(w3.w, a4.w, acc[b].w);
            }
        }
        const float4* WS = (const float4*)g_gsrcT;
        const float4* Sv = (const float4*)src;
        for (int kv = 0; kv < DMV; kv++) {
            const int k = kv * 4;
            float4 w0 = WS[(k + 0) * DMV + dg];
            float4 w1 = WS[(k + 1) * DMV + dg];
            float4 w2 = WS[(k + 2) * DMV + dg];
            float4 w3 = WS[(k + 3) * DMV + dg];
#pragma unroll
            for (int b = 0; b < 4; b++) {
                float4 a4 = Sv[(bg + b) * DMV + kv];
                acc[b].x = fmaf(w0.x, a4.x, acc[b].x);
                acc[b].y = fmaf(w0.y, a4.x, acc[b].y);
                acc[b].z = fmaf(w0.z, a4.x, acc[b].z);
                acc[b].w = fmaf(w0.w, a4.x, acc[b].w);
                acc[b].x = fmaf(w1.x, a4.y, acc[b].x);
                acc[b].y = fmaf(w1.y, a4.y, acc[b].y);
                acc[b].z = fmaf(w1.z, a4.y, acc[b].z);
                acc[b].w = fmaf(w1.w, a4.y, acc[b].w);
                acc[b].x = fmaf(w2.x, a4.z, acc[b].x);
                acc[b].y = fmaf(w2.y, a4.z, acc[b].y);
                acc[b].z = fmaf(w2.z, a4.z, acc[b].z);
                acc[b].w = fmaf(w2.w, a4.z, acc[b].w);
                acc[b].x = fmaf(w3.x, a4.w, acc[b].x);
                acc[b].y = fmaf(w3.y, a4.w, acc[b].y);
                acc[b].z = fmaf(w3.z, a4.w, acc[b].z);
                acc[b].w = fmaf(w3.w, a4.w, acc[b].w);
            }
        }
    }
    __syncthreads();   // reads of mctx complete (uniform)
    float* hbuf = mx;  // overlay
    if (act) {
#pragma unroll
        for (int b = 0; b < 4; b++) {
            float4 r;
            r.x = fmaxf(acc[b].x, 0.f); r.y = fmaxf(acc[b].y, 0.f);
            r.z = fmaxf(acc[b].z, 0.f); r.w = fmaxf(acc[b].w, 0.f);
            ((float4*)hbuf)[(bg + b) * DMV + dg] = r;
        }
    }
    __syncthreads();

    // ===== phase 6: out = fc2 @ h + fc2_b ===================================
    if (act) {
        {
            float4 fb = ((const float4*)fc2b)[dg];
#pragma unroll
            for (int b = 0; b < 4; b++) acc[b] = fb;
        }
        const float4* WF = (const float4*)g_fc2T;
        const float4* Hv = (const float4*)hbuf;
        for (int kv = 0; kv < DMV; kv++) {
            const int k = kv * 4;
            float4 w0 = WF[(k + 0) * DMV + dg];
            float4 w1 = WF[(k + 1) * DMV + dg];
            float4 w2 = WF[(k + 2) * DMV + dg];
            float4 w3 = WF[(k + 3) * DMV + dg];
#pragma unroll
            for (int b = 0; b < 4; b++) {
                float4 a4 = Hv[(bg + b) * DMV + kv];
                acc[b].x = fmaf(w0.x, a4.x, acc[b].x);
                acc[b].y = fmaf(w0.y, a4.x, acc[b].y);
                acc[b].z = fmaf(w0.z, a4.x, acc[b].z);
                acc[b].w = fmaf(w0.w, a4.x, acc[b].w);
                acc[b].x = fmaf(w1.x, a4.y, acc[b].x);
                acc[b].y = fmaf(w1.y, a4.y, acc[b].y);
                acc[b].z = fmaf(w1.z, a4.y, acc[b].z);
                acc[b].w = fmaf(w1.w, a4.y, acc[b].w);
                acc[b].x = fmaf(w2.x, a4.z, acc[b].x);
                acc[b].y = fmaf(w2.y, a4.z, acc[b].y);
                acc[b].z = fmaf(w2.z, a4.z, acc[b].z);
                acc[b].w = fmaf(w2.w, a4.z, acc[b].w);
                acc[b].x = fmaf(w3.x, a4.w, acc[b].x);
                acc[b].y = fmaf(w3.y, a4.w, acc[b].y);
                acc[b].z = fmaf(w3.z, a4.w, acc[b].z);
                acc[b].w = fmaf(w3.w, a4.w, acc[b].w);
            }
        }
#pragma unroll
        for (int b = 0; b < 4; b++)
            ((float4*)out)[(size_t)(b0 + bg + b) * DMV + dg] = acc[b];
    }
}

// ---------------- launch ----------------
extern "C" void kernel_launch(void* const* d_in, const int* in_sizes, int n_in,
                              void* d_out, int out_size) {
    const float* msg   = (const float*)d_in[0];   // (B,N,D)
    const float* timeb = (const float*)d_in[1];   // (B,N)
    // d_in[2] = memory (unused by reference)
    const float* tw    = (const float*)d_in[3];   // (T,)
    const float* tb    = (const float*)d_in[4];   // (T,)
    const float* ipw   = (const float*)d_in[5];   // (3E,E)
    const float* ipb   = (const float*)d_in[6];   // (3E,)
    const float* opw   = (const float*)d_in[7];   // (E,E)
    const float* opb   = (const float*)d_in[8];   // (E,)
    const float* fc1w  = (const float*)d_in[9];   // (D,E+D)
    const float* fc1b  = (const float*)d_in[10];  // (D,)
    const float* fc2w  = (const float*)d_in[11];  // (D,D)
    const float* fc2b  = (const float*)d_in[12];  // (D,)
    float* out = (float*)d_out;

    cudaFuncSetAttribute(fused, cudaFuncAttributeMaxDynamicSharedMemorySize, FS_SMEM);

    prep1<<<(P1_TOT + 255) / 256, 256>>>(ipw, ipb, tb, opw, opb);
    prep2<<<(P2_TOT + 255) / 256, 256>>>(ipw, fc1w, fc1b, fc2w);

    fused<<<BB / 16, 288, FS_SMEM>>>(msg, timeb, tw, tb, fc1b, fc2b, out);
}